// round 8
// baseline (speedup 1.0000x reference)
#include <cuda_runtime.h>
#include <cuda_bf16.h>

// PairwiseMax: B=4096, D1=256, D2=256, F=128
// out[b, 0:256]   = x0[b,i] >= 0 ? x0[b,i]*max(x1[b,:]) : x0[b,i]*min(x1[b,:])
// out[b, 256:384] = x2[b,:]
//
// R8: raise in-flight bytes. 2 rows per warp, 10 front-batched LDG.128
// per lane before any scoreboard wait (~140 KB/SM in flight, 2x R5).
// 512 blocks x 128 threads = 2048 warps. REDUX-based reduction (R7),
// branchless select, early x2 stores.

#define B_ROWS 4096
#define WARPS_PER_BLOCK 4
#define THREADS (WARPS_PER_BLOCK * 32)                 // 128
#define ROWS_PER_WARP 2
#define BLOCKS (B_ROWS / (WARPS_PER_BLOCK * ROWS_PER_WARP))  // 512

// Monotone map: float total order -> unsigned total order.
__device__ __forceinline__ unsigned enc_ord(float f) {
    unsigned u = __float_as_uint(f);
    return u ^ ((unsigned)((int)u >> 31) | 0x80000000u);
}
__device__ __forceinline__ float dec_ord(unsigned k) {
    return __uint_as_float(k ^ ((unsigned)(((int)~k) >> 31) | 0x80000000u));
}

__device__ __forceinline__ float f4max(float4 v) {
    return fmaxf(fmaxf(v.x, v.y), fmaxf(v.z, v.w));
}
__device__ __forceinline__ float f4min(float4 v) {
    return fminf(fminf(v.x, v.y), fminf(v.z, v.w));
}

__global__ __launch_bounds__(THREADS) void pairwise_max_kernel(
    const float4* __restrict__ x0v,   // [B, 64] float4
    const float4* __restrict__ x1v,   // [B, 64] float4
    const float4* __restrict__ x2v,   // [B, 32] float4
    float4* __restrict__ outv)        // [B, 96] float4
{
    const int warp_id = threadIdx.x >> 5;
    const int lane    = threadIdx.x & 31;
    const int row0    = (blockIdx.x * WARPS_PER_BLOCK + warp_id) * ROWS_PER_WARP;
    const int row1    = row0 + 1;

    const float4* x1r0 = x1v + (size_t)row0 * 64;
    const float4* x1r1 = x1v + (size_t)row1 * 64;
    const float4* x0r0 = x0v + (size_t)row0 * 64;
    const float4* x0r1 = x0v + (size_t)row1 * 64;
    const float4* x2r0 = x2v + (size_t)row0 * 32;
    const float4* x2r1 = x2v + (size_t)row1 * 32;
    float4* outr0 = outv + (size_t)row0 * 96;
    float4* outr1 = outv + (size_t)row1 * 96;

    // ---- Front-batch all 10 independent loads (no consumer in between) ----
    float4 a0 = x1r0[lane];
    float4 b0 = x1r0[lane + 32];
    float4 a1 = x1r1[lane];
    float4 b1 = x1r1[lane + 32];
    float4 c0 = x0r0[lane];
    float4 d0 = x0r0[lane + 32];
    float4 c1 = x0r1[lane];
    float4 d1 = x0r1[lane + 32];
    float4 e0 = x2r0[lane];
    float4 e1 = x2r1[lane];

    // ---- Local reductions (both rows, independent chains) ----
    float lmx0 = fmaxf(f4max(a0), f4max(b0));
    float lmn0 = fminf(f4min(a0), f4min(b0));
    float lmx1 = fmaxf(f4max(a1), f4max(b1));
    float lmn1 = fminf(f4min(a1), f4min(b1));

    // x2 passthrough stores: independent of reductions, drain early.
    outr0[lane + 64] = e0;
    outr1[lane + 64] = e1;

    // ---- Warp reductions via integer REDUX (4 independent ops) ----
    const float mx0 = dec_ord(__reduce_max_sync(0xFFFFFFFFu, enc_ord(lmx0)));
    const float mn0 = dec_ord(__reduce_min_sync(0xFFFFFFFFu, enc_ord(lmn0)));
    const float mx1 = dec_ord(__reduce_max_sync(0xFFFFFFFFu, enc_ord(lmx1)));
    const float mn1 = dec_ord(__reduce_min_sync(0xFFFFFFFFu, enc_ord(lmn1)));

    // ---- Branchless scale + stores ----
    float4 o;
    o.x = fmaxf(c0.x * mx0, c0.x * mn0);
    o.y = fmaxf(c0.y * mx0, c0.y * mn0);
    o.z = fmaxf(c0.z * mx0, c0.z * mn0);
    o.w = fmaxf(c0.w * mx0, c0.w * mn0);
    outr0[lane] = o;

    o.x = fmaxf(d0.x * mx0, d0.x * mn0);
    o.y = fmaxf(d0.y * mx0, d0.y * mn0);
    o.z = fmaxf(d0.z * mx0, d0.z * mn0);
    o.w = fmaxf(d0.w * mx0, d0.w * mn0);
    outr0[lane + 32] = o;

    o.x = fmaxf(c1.x * mx1, c1.x * mn1);
    o.y = fmaxf(c1.y * mx1, c1.y * mn1);
    o.z = fmaxf(c1.z * mx1, c1.z * mn1);
    o.w = fmaxf(c1.w * mx1, c1.w * mn1);
    outr1[lane] = o;

    o.x = fmaxf(d1.x * mx1, d1.x * mn1);
    o.y = fmaxf(d1.y * mx1, d1.y * mn1);
    o.z = fmaxf(d1.z * mx1, d1.z * mn1);
    o.w = fmaxf(d1.w * mx1, d1.w * mn1);
    outr1[lane + 32] = o;
}

extern "C" void kernel_launch(void* const* d_in, const int* in_sizes, int n_in,
                              void* d_out, int out_size)
{
    const float4* x0v = (const float4*)d_in[0];
    const float4* x1v = (const float4*)d_in[1];
    const float4* x2v = (const float4*)d_in[2];
    float4* outv = (float4*)d_out;

    pairwise_max_kernel<<<BLOCKS, THREADS>>>(x0v, x1v, x2v, outv);
}

// round 9
// speedup vs baseline: 1.0156x; 1.0156x over previous
#include <cuda_runtime.h>
#include <cuda_bf16.h>

// PairwiseMax: B=4096, D1=256, D2=256, F=128
// out[b, 0:256]   = x0[b,i] >= 0 ? x0[b,i]*max(x1[b,:]) : x0[b,i]*min(x1[b,:])
// out[b, 256:384] = x2[b,:]
//
// R9: R5/R7 geometry (1024 blocks x 128 thr, warp-per-row), consume loads
// in L1tex-queue order: reduce on x1 (loads 1-2) immediately; x0/x2
// (loads 3-5) land under the REDUX ops; x2 store sunk to the end.
// Previous rounds stalled on the FULL load queue (early e-store) before
// starting the reduction.

#define B_ROWS 4096
#define WARPS_PER_BLOCK 4
#define THREADS (WARPS_PER_BLOCK * 32)           // 128
#define BLOCKS (B_ROWS / WARPS_PER_BLOCK)        // 1024

// Monotone map: float total order -> unsigned total order.
__device__ __forceinline__ unsigned enc_ord(float f) {
    unsigned u = __float_as_uint(f);
    return u ^ ((unsigned)((int)u >> 31) | 0x80000000u);
}
__device__ __forceinline__ float dec_ord(unsigned k) {
    return __uint_as_float(k ^ ((unsigned)(((int)~k) >> 31) | 0x80000000u));
}

__global__ __launch_bounds__(THREADS) void pairwise_max_kernel(
    const float4* __restrict__ x0v,   // [B, 64] float4
    const float4* __restrict__ x1v,   // [B, 64] float4
    const float4* __restrict__ x2v,   // [B, 32] float4
    float4* __restrict__ outv)        // [B, 96] float4
{
    const int warp_id = threadIdx.x >> 5;
    const int lane    = threadIdx.x & 31;
    const int row     = blockIdx.x * WARPS_PER_BLOCK + warp_id;  // exact 4096

    const float4* x1row  = x1v + (size_t)row * 64;
    const float4* x0row  = x0v + (size_t)row * 64;
    const float4* x2row  = x2v + (size_t)row * 32;
    float4*       outrow = outv + (size_t)row * 96;

    // Issue x1 loads FIRST (their consumers come first), then x0/x2.
    float4 a = x1row[lane];
    float4 b = x1row[lane + 32];
    float4 c = x0row[lane];
    float4 d = x0row[lane + 32];
    float4 e = x2row[lane];

    // First scoreboard wait: only a,b (front of the L1tex queue).
    float lmx = fmaxf(fmaxf(fmaxf(a.x, a.y), fmaxf(a.z, a.w)),
                      fmaxf(fmaxf(b.x, b.y), fmaxf(b.z, b.w)));
    float lmn = fminf(fminf(fminf(a.x, a.y), fminf(a.z, a.w)),
                      fminf(fminf(b.x, b.y), fminf(b.z, b.w)));

    // c, d, e continue landing while REDUX executes.
    const float mx = dec_ord(__reduce_max_sync(0xFFFFFFFFu, enc_ord(lmx)));
    const float mn = dec_ord(__reduce_min_sync(0xFFFFFFFFu, enc_ord(lmn)));

    // Branchless: mx >= mn, so the selected product is the larger one.
    float4 oc, od;
    oc.x = fmaxf(c.x * mx, c.x * mn);
    oc.y = fmaxf(c.y * mx, c.y * mn);
    oc.z = fmaxf(c.z * mx, c.z * mn);
    oc.w = fmaxf(c.w * mx, c.w * mn);
    od.x = fmaxf(d.x * mx, d.x * mn);
    od.y = fmaxf(d.y * mx, d.y * mn);
    od.z = fmaxf(d.z * mx, d.z * mn);
    od.w = fmaxf(d.w * mx, d.w * mn);

    outrow[lane]      = oc;
    outrow[lane + 32] = od;
    outrow[lane + 64] = e;   // x2 passthrough, deepest-queued load consumed last
}

extern "C" void kernel_launch(void* const* d_in, const int* in_sizes, int n_in,
                              void* d_out, int out_size)
{
    const float4* x0v = (const float4*)d_in[0];
    const float4* x1v = (const float4*)d_in[1];
    const float4* x2v = (const float4*)d_in[2];
    float4* outv = (float4*)d_out;

    pairwise_max_kernel<<<BLOCKS, THREADS>>>(x0v, x1v, x2v, outv);
}